// round 8
// baseline (speedup 1.0000x reference)
#include <cuda_runtime.h>
#include <math.h>
#include <stdint.h>

// Problem constants
#define BB 4
#define SS 2048
#define DD 1024
#define HH 16
#define DH 64
#define MROWS (BB * SS)      // 8192
#define N1 (3 * DD)          // 3072

// Scratch (allocation-free: device globals)
__device__ float g_qkv[(size_t)MROWS * N1];   // [B*S, 3D] tf32-rounded
__device__ float g_att[(size_t)MROWS * DD];   // [B*S, D]  tf32-rounded
__device__ float g_w1r[(size_t)N1 * DD];      // w_in rounded
__device__ float g_w2r[(size_t)DD * DD];      // w_out rounded

// ===========================================================================
// helpers
// ===========================================================================
__device__ __forceinline__ uint32_t smem_u32(const void* p) {
    uint32_t a;
    asm("{ .reg .u64 t; cvta.to.shared.u64 t, %1; cvt.u32.u64 %0, t; }"
        : "=r"(a) : "l"(p));
    return a;
}
__device__ __forceinline__ float tf32_rna(float x) {
    uint32_t u;
    asm("cvt.rna.tf32.f32 %0, %1;" : "=r"(u) : "f"(x));
    return __uint_as_float(u);
}
__device__ __forceinline__ uint32_t tf32r_u(uint32_t u) {
    uint32_t o;
    asm("cvt.rna.tf32.f32 %0, %1;" : "=r"(o) : "f"(__uint_as_float(u)));
    return o;
}

#define MMA_TF32(acc, a0, a1, a2, a3, b0, b1) \
    asm volatile( \
        "mma.sync.aligned.m16n8k8.row.col.f32.tf32.tf32.f32 " \
        "{%0,%1,%2,%3}, {%4,%5,%6,%7}, {%8,%9}, {%0,%1,%2,%3};" \
        : "+f"((acc)[0]), "+f"((acc)[1]), "+f"((acc)[2]), "+f"((acc)[3]) \
        : "r"(a0), "r"(a1), "r"(a2), "r"(a3), "r"(b0), "r"(b1))

#define LDSM4(r, a) \
    asm volatile("ldmatrix.sync.aligned.m8n8.x4.shared.b16 {%0,%1,%2,%3}, [%4];" \
        : "=r"((r)[0]), "=r"((r)[1]), "=r"((r)[2]), "=r"((r)[3]) : "r"(a))

#define CP_A16(dst, src) \
    asm volatile("cp.async.cg.shared.global [%0], [%1], 16;" \
                 :: "r"(dst), "l"(src) : "memory")
#define CP_COMMIT() asm volatile("cp.async.commit_group;" ::: "memory")
#define CP_WAIT1()  asm volatile("cp.async.wait_group 1;" ::: "memory")
#define CP_WAIT0()  asm volatile("cp.async.wait_group 0;" ::: "memory")

// ===========================================================================
// weight rounding prep (w_in, w_out only — x is rounded in-GEMM)
// ===========================================================================
__global__ void round2_tf32(const float* __restrict__ w1, float* __restrict__ w1r,
                            const float* __restrict__ w2, float* __restrict__ w2r)
{
    const int n1 = N1 * DD / 4, n2 = DD * DD / 4;
    int i = blockIdx.x * blockDim.x + threadIdx.x;
    const float4* s; float4* d; int j;
    if (i < n1)           { s = (const float4*)w1; d = (float4*)w1r; j = i; }
    else if (i < n1 + n2) { s = (const float4*)w2; d = (float4*)w2r; j = i - n1; }
    else return;
    float4 v = s[j];
    v.x = tf32_rna(v.x); v.y = tf32_rna(v.y);
    v.z = tf32_rna(v.z); v.w = tf32_rna(v.w);
    d[j] = v;
}

// ===========================================================================
// tf32 mma.sync GEMM: C[M,N] = A[M,K] @ B[N,K]^T + bias[N]
// CTA 128x128, BK=32, 3-stage cp.async, 8 warps (4Mx2N), warp tile 32x64.
// ROUND_A: A loaded raw fp32; fragments rounded to tf32 in-register.
// B must be pre-rounded. ROUND_OUT: round outputs (feeds next tf32 stage).
// ===========================================================================
#define STAGES  3
#define BKC     32
#define PAD_S   36
#define TILE_F  (128 * PAD_S)
#define STAGE_F (2 * TILE_F)
#define GSMEM_BYTES (STAGES * STAGE_F * 4)

template<int ROUND_OUT, int ROUND_A>
__global__ __launch_bounds__(256, 2) void gemm_tf32mma(
    const float* __restrict__ A, const float* __restrict__ Bm,
    const float* __restrict__ bias, float* __restrict__ C,
    int M, int N, int K)
{
    extern __shared__ float sm[];
    const uint32_t smb = smem_u32(sm);
    const int tid  = threadIdx.x;
    const int lane = tid & 31, wid = tid >> 5;
    const int g = lane >> 2, t = lane & 3;
    const int wm = wid & 3, wn = wid >> 2;
    const int bm = blockIdx.y * 128, bn = blockIdx.x * 128;

    const int lrow = tid >> 3;
    const int lc4  = tid & 7;
    const float* aBase = A  + (size_t)(bm + lrow) * K + lc4 * 4;
    const float* bBase = Bm + (size_t)(bn + lrow) * K + lc4 * 4;
    const uint32_t dA = smb + (uint32_t)((lrow * PAD_S + lc4 * 4) * 4);

    uint32_t aAddr0, bAddr0;
    {
        int ar = wm * 32 + (lane & 15);
        int ac = (lane >> 4) * 4;
        aAddr0 = smb + (uint32_t)((ar * PAD_S + ac) * 4);
        int br = wn * 64 + (lane & 7) + ((lane & 16) >> 1);
        int bc = (lane & 8) >> 1;
        bAddr0 = smb + (uint32_t)((TILE_F + br * PAD_S + bc) * 4);
    }

    float acc[2][8][4];
    #pragma unroll
    for (int mt = 0; mt < 2; mt++)
        #pragma unroll
        for (int nt = 0; nt < 8; nt++)
            #pragma unroll
            for (int r = 0; r < 4; r++) acc[mt][nt][r] = 0.f;

#define ISSUE_CHUNK(c, s) do { \
    uint32_t _b = dA + (uint32_t)(s) * (STAGE_F * 4); \
    const float* _pa = aBase + (c) * BKC; \
    const float* _pb = bBase + (c) * BKC; \
    _Pragma("unroll") \
    for (int _i = 0; _i < 4; _i++) { \
        CP_A16(_b + _i * (32 * PAD_S * 4),              _pa + (size_t)_i * 32 * K); \
        CP_A16(_b + TILE_F * 4 + _i * (32 * PAD_S * 4), _pb + (size_t)_i * 32 * K); \
    } \
    CP_COMMIT(); \
} while (0)

    const int NCH = K / BKC;
    ISSUE_CHUNK(0, 0);
    ISSUE_CHUNK(1, 1);

    for (int c = 0; c < NCH; c++) {
        if (c + 1 < NCH) { CP_WAIT1(); } else { CP_WAIT0(); }
        __syncthreads();
        if (c + 2 < NCH) ISSUE_CHUNK(c + 2, (c + 2) % STAGES);
        const uint32_t soff = (uint32_t)((c % STAGES) * (STAGE_F * 4));
        #pragma unroll
        for (int ks = 0; ks < 4; ks++) {
            const uint32_t koff = soff + ks * 32;
            uint32_t af[2][4], bq[4][4];
            LDSM4(af[0], aAddr0 + koff);
            LDSM4(af[1], aAddr0 + koff + 16 * PAD_S * 4);
            if (ROUND_A) {
                #pragma unroll
                for (int mt = 0; mt < 2; mt++)
                    #pragma unroll
                    for (int r = 0; r < 4; r++)
                        af[mt][r] = tf32r_u(af[mt][r]);
            }
            #pragma unroll
            for (int p = 0; p < 4; p++)
                LDSM4(bq[p], bAddr0 + koff + p * (16 * PAD_S * 4));
            #pragma unroll
            for (int mt = 0; mt < 2; mt++)
                #pragma unroll
                for (int nt = 0; nt < 8; nt++)
                    MMA_TF32(acc[mt][nt],
                             af[mt][0], af[mt][1], af[mt][2], af[mt][3],
                             bq[nt >> 1][(nt & 1) * 2], bq[nt >> 1][(nt & 1) * 2 + 1]);
        }
    }
#undef ISSUE_CHUNK

    const int col0 = bn + wn * 64;
    #pragma unroll
    for (int mt = 0; mt < 2; mt++) {
        #pragma unroll
        for (int h = 0; h < 2; h++) {
            int row = bm + wm * 32 + mt * 16 + g + h * 8;
            float* cp = C + (size_t)row * N + col0;
            #pragma unroll
            for (int nt = 0; nt < 8; nt++) {
                int cc = nt * 8 + t * 2;
                float2 bz = *(const float2*)(bias + col0 + cc);
                float2 v;
                v.x = acc[mt][nt][h * 2 + 0] + bz.x;
                v.y = acc[mt][nt][h * 2 + 1] + bz.y;
                if (ROUND_OUT) { v.x = tf32_rna(v.x); v.y = tf32_rna(v.y); }
                *(float2*)(cp + cc) = v;
            }
        }
    }
}

// ===========================================================================
// Tensor-core flash attention. Block = (128-row q-tile, head, batch), 8 warps,
// warp owns 16 rows. K/V (64 keys/tile) cp.async double-buffered.
// exp2-domain softmax; warp-level causal tile skip.
// LPT scheduling: qt reversed so heavy (large-qt) CTAs launch first.
// ===========================================================================
#define QT  128
#define KST 68
#define VST 72
#define AP_OFF  0
#define AK_OFF(s) (QT * KST + (s) * 64 * KST)
#define AV_OFF(s) (QT * KST + 2 * 64 * KST + (s) * 64 * VST)
#define ASMEM_BYTES ((QT * KST + 2 * 64 * KST + 2 * 64 * VST) * 4)   // 106496

__global__ __launch_bounds__(256, 2) void flash_attn_tc(const int* __restrict__ causal_flag)
{
    extern __shared__ float smf[];
    const uint32_t sb = smem_u32(smf);
    float* Ps = smf + AP_OFF;

    const int qt = gridDim.x - 1 - blockIdx.x;   // heavy CTAs first (LPT)
    const int h = blockIdx.y, b = blockIdx.z;
    const int tid = threadIdx.x, lane = tid & 31, w = tid >> 5;
    const int g = lane >> 2, t = lane & 3;
    const int causal = *causal_flag;
    const int r0 = w * 16 + g, r1 = r0 + 8;
    const int rowmin = qt * QT + w * 16;

    const int ktmax = causal ? min(2 * qt + 1, SS / 64 - 1) : (SS / 64 - 1);
    const float* kvb = g_qkv + (size_t)(b * SS) * N1 + DD + h * DH;
    const int irow = tid >> 4;
    const int ic4  = tid & 15;

    const uint32_t pAddr = sb + (uint32_t)(((w * 16 + (lane & 15)) * KST
                                            + (lane >> 4) * 4) * 4);
    const uint32_t kAddr = sb + (uint32_t)((AK_OFF(0)
                         + ((lane & 7) + ((lane & 16) >> 1)) * KST
                         + ((lane & 8) >> 1)) * 4);

#define ISSUE_KV(kt, s) do { \
    const float* _kb = kvb + (size_t)((kt) * 64) * N1; \
    uint32_t _kd = sb + (uint32_t)(AK_OFF(s) * 4); \
    uint32_t _vd = sb + (uint32_t)(AV_OFF(s) * 4); \
    _Pragma("unroll") \
    for (int _i = 0; _i < 4; _i++) { \
        int _r = irow + _i * 16; \
        const float* _src = _kb + (size_t)_r * N1 + ic4 * 4; \
        CP_A16(_kd + (uint32_t)((_r * KST + ic4 * 4) * 4), _src); \
        CP_A16(_vd + (uint32_t)((_r * VST + ic4 * 4) * 4), _src + DD); \
    } \
    CP_COMMIT(); \
} while (0)

    ISSUE_KV(0, 0);

    // stage Q * (0.125 * log2 e), re-rounded to tf32 (exp2-domain scores)
    {
        const float qs = 0.125f * 1.4426950408889634f;
        const float* qb = g_qkv + (size_t)(b * SS + qt * QT) * N1 + h * DH;
        #pragma unroll
        for (int i = 0; i < 8; i++) {
            int fid = tid + i * 256, row = fid >> 4, c4 = fid & 15;
            float4 v = *(const float4*)(qb + (size_t)row * N1 + c4 * 4);
            float* d = Ps + row * KST + c4 * 4;
            d[0] = tf32_rna(v.x * qs); d[1] = tf32_rna(v.y * qs);
            d[2] = tf32_rna(v.z * qs); d[3] = tf32_rna(v.w * qs);
        }
    }
    __syncthreads();
    uint32_t qf[8][4];
    #pragma unroll
    for (int ks = 0; ks < 8; ks++) LDSM4(qf[ks], pAddr + ks * 32);

    float m0 = -INFINITY, m1 = -INFINITY, l0 = 0.f, l1 = 0.f;
    float oa[8][4];
    #pragma unroll
    for (int nt = 0; nt < 8; nt++)
        #pragma unroll
        for (int r = 0; r < 4; r++) oa[nt][r] = 0.f;

    for (int kt = 0; kt <= ktmax; kt++) {
        const int cur = kt & 1;
        CP_WAIT0();
        __syncthreads();
        if (kt < ktmax) ISSUE_KV(kt + 1, cur ^ 1);

        if (causal && kt * 64 > rowmin + 15) continue;

        const float* Vs = smf + AV_OFF(cur);
        const uint32_t kOff = (uint32_t)(cur * (64 * KST * 4));

        // ---- S = Q K^T (log2-domain) ----
        float sc[8][4];
        #pragma unroll
        for (int nt = 0; nt < 8; nt++)
            #pragma unroll
            for (int r = 0; r < 4; r++) sc[nt][r] = 0.f;
        #pragma unroll
        for (int ks = 0; ks < 8; ks++) {
            uint32_t kb[4][4];
            #pragma unroll
            for (int p = 0; p < 4; p++)
                LDSM4(kb[p], kAddr + kOff + ks * 32 + p * (16 * KST * 4));
            #pragma unroll
            for (int nt = 0; nt < 8; nt++)
                MMA_TF32(sc[nt], qf[ks][0], qf[ks][1], qf[ks][2], qf[ks][3],
                         kb[nt >> 1][(nt & 1) * 2], kb[nt >> 1][(nt & 1) * 2 + 1]);
        }

        if (causal && kt * 64 + 63 > rowmin) {
            const int r0g = rowmin + g, r1g = r0g + 8;
            #pragma unroll
            for (int nt = 0; nt < 8; nt++) {
                int c0 = kt * 64 + nt * 8 + 2 * t, c1 = c0 + 1;
                if (c0 > r0g) sc[nt][0] = -INFINITY;
                if (c1 > r0g) sc[nt][1] = -INFINITY;
                if (c0 > r1g) sc[nt][2] = -INFINITY;
                if (c1 > r1g) sc[nt][3] = -INFINITY;
            }
        }

        // ---- online softmax (exp2 domain) ----
        float mx0 = m0, mx1 = m1;
        #pragma unroll
        for (int nt = 0; nt < 8; nt++) {
            mx0 = fmaxf(mx0, fmaxf(sc[nt][0], sc[nt][1]));
            mx1 = fmaxf(mx1, fmaxf(sc[nt][2], sc[nt][3]));
        }
        mx0 = fmaxf(mx0, __shfl_xor_sync(0xffffffffu, mx0, 1));
        mx0 = fmaxf(mx0, __shfl_xor_sync(0xffffffffu, mx0, 2));
        mx1 = fmaxf(mx1, __shfl_xor_sync(0xffffffffu, mx1, 1));
        mx1 = fmaxf(mx1, __shfl_xor_sync(0xffffffffu, mx1, 2));
        float a0 = exp2f(m0 - mx0), a1 = exp2f(m1 - mx1);
        m0 = mx0; m1 = mx1;
        l0 *= a0; l1 *= a1;

        float s0 = 0.f, s1 = 0.f;
        #pragma unroll
        for (int nt = 0; nt < 8; nt++) {
            float p00 = exp2f(sc[nt][0] - m0);
            float p01 = exp2f(sc[nt][1] - m0);
            float p10 = exp2f(sc[nt][2] - m1);
            float p11 = exp2f(sc[nt][3] - m1);
            s0 += p00 + p01; s1 += p10 + p11;
            *(float2*)(Ps + r0 * KST + nt * 8 + 2 * t) =
                make_float2(tf32_rna(p00), tf32_rna(p01));
            *(float2*)(Ps + r1 * KST + nt * 8 + 2 * t) =
                make_float2(tf32_rna(p10), tf32_rna(p11));
            oa[nt][0] *= a0; oa[nt][1] *= a0;
            oa[nt][2] *= a1; oa[nt][3] *= a1;
        }
        s0 += __shfl_xor_sync(0xffffffffu, s0, 1);
        s0 += __shfl_xor_sync(0xffffffffu, s0, 2);
        s1 += __shfl_xor_sync(0xffffffffu, s1, 1);
        s1 += __shfl_xor_sync(0xffffffffu, s1, 2);
        l0 += s0; l1 += s1;
        __syncwarp();

        // ---- O += P V  (V row-major [key][d], stride VST) ----
        #pragma unroll
        for (int ks = 0; ks < 8; ks++) {
            uint32_t pf[4];
            LDSM4(pf, pAddr + ks * 32);
            #pragma unroll
            for (int nt = 0; nt < 8; nt++) {
                uint32_t b0 = __float_as_uint(Vs[(ks * 8 + t) * VST + nt * 8 + g]);
                uint32_t b1 = __float_as_uint(Vs[(ks * 8 + t + 4) * VST + nt * 8 + g]);
                MMA_TF32(oa[nt], pf[0], pf[1], pf[2], pf[3], b0, b1);
            }
        }
        __syncwarp();
    }
#undef ISSUE_KV

    float i0 = 1.f / l0, i1 = 1.f / l1;
    float* ob = g_att + (size_t)(b * SS + qt * QT) * DD + h * DH;
    #pragma unroll
    for (int nt = 0; nt < 8; nt++) {
        *(float2*)(ob + (size_t)r0 * DD + nt * 8 + 2 * t) =
            make_float2(tf32_rna(oa[nt][0] * i0), tf32_rna(oa[nt][1] * i0));
        *(float2*)(ob + (size_t)r1 * DD + nt * 8 + 2 * t) =
            make_float2(tf32_rna(oa[nt][2] * i1), tf32_rna(oa[nt][3] * i1));
    }
}

// ---------------------------------------------------------------------------
extern "C" void kernel_launch(void* const* d_in, const int* in_sizes, int n_in,
                              void* d_out, int out_size)
{
    const float* x     = (const float*)d_in[0];
    const float* w_in  = (const float*)d_in[1];
    const float* b_in  = (const float*)d_in[2];
    const float* w_out = (const float*)d_in[3];
    const float* b_out = (const float*)d_in[4];
    const int*   cmask = (const int*)d_in[5];
    float* out = (float*)d_out;

    float *qkv, *att, *w1r, *w2r;
    cudaGetSymbolAddress((void**)&qkv, g_qkv);
    cudaGetSymbolAddress((void**)&att, g_att);
    cudaGetSymbolAddress((void**)&w1r, g_w1r);
    cudaGetSymbolAddress((void**)&w2r, g_w2r);

    cudaFuncSetAttribute((const void*)gemm_tf32mma<1, 1>,
                         cudaFuncAttributeMaxDynamicSharedMemorySize, GSMEM_BYTES);
    cudaFuncSetAttribute((const void*)gemm_tf32mma<0, 0>,
                         cudaFuncAttributeMaxDynamicSharedMemorySize, GSMEM_BYTES);
    cudaFuncSetAttribute((const void*)flash_attn_tc,
                         cudaFuncAttributeMaxDynamicSharedMemorySize, ASMEM_BYTES);

    // 0) round weights only to tf32-exact fp32 (x is rounded in-GEMM)
    {
        int tot = N1 * DD / 4 + DD * DD / 4;
        round2_tf32<<<(tot + 255) / 256, 256>>>(w_in, w1r, w_out, w2r);
    }

    // 1) QKV projection: raw x, A-fragments rounded in-register; output rounded
    gemm_tf32mma<1, 1><<<dim3(N1 / 128, MROWS / 128), 256, GSMEM_BYTES>>>(
        x, w1r, b_in, qkv, MROWS, N1, DD);

    // 2) Causal multi-head flash attention (tensor cores, LPT CTA order)
    flash_attn_tc<<<dim3(SS / QT, HH, BB), 256, ASMEM_BYTES>>>(cmask);

    // 3) Output projection (both inputs pre-rounded; plain fp32 output)
    gemm_tf32mma<0, 0><<<dim3(DD / 128, MROWS / 128), 256, GSMEM_BYTES>>>(
        att, w2r, b_out, out, MROWS, DD, DD);
}

// round 9
// speedup vs baseline: 1.7205x; 1.7205x over previous
#include <cuda_runtime.h>
#include <cuda_fp16.h>
#include <math.h>
#include <stdint.h>

// Problem constants
#define BB 4
#define SS 2048
#define DD 1024
#define HH 16
#define DH 64
#define MROWS (BB * SS)      // 8192
#define N1 (3 * DD)          // 3072

// Scratch (allocation-free: device globals), all fp16 inter-stage
__device__ __half g_qkv[(size_t)MROWS * N1];   // [B*S, 3D]
__device__ __half g_att[(size_t)MROWS * DD];   // [B*S, D]
__device__ __half g_xh [(size_t)MROWS * DD];
__device__ __half g_w1h[(size_t)N1 * DD];
__device__ __half g_w2h[(size_t)DD * DD];

// ===========================================================================
// helpers
// ===========================================================================
__device__ __forceinline__ uint32_t smem_u32(const void* p) {
    uint32_t a;
    asm("{ .reg .u64 t; cvta.to.shared.u64 t, %1; cvt.u32.u64 %0, t; }"
        : "=r"(a) : "l"(p));
    return a;
}

#define MMA_F16(acc, a0, a1, a2, a3, b0, b1) \
    asm volatile( \
        "mma.sync.aligned.m16n8k16.row.col.f32.f16.f16.f32 " \
        "{%0,%1,%2,%3}, {%4,%5,%6,%7}, {%8,%9}, {%0,%1,%2,%3};" \
        : "+f"((acc)[0]), "+f"((acc)[1]), "+f"((acc)[2]), "+f"((acc)[3]) \
        : "r"(a0), "r"(a1), "r"(a2), "r"(a3), "r"(b0), "r"(b1))

#define LDSM4(r, a) \
    asm volatile("ldmatrix.sync.aligned.m8n8.x4.shared.b16 {%0,%1,%2,%3}, [%4];" \
        : "=r"((r)[0]), "=r"((r)[1]), "=r"((r)[2]), "=r"((r)[3]) : "r"(a))
#define LDSM4T(r, a) \
    asm volatile("ldmatrix.sync.aligned.m8n8.x4.trans.shared.b16 {%0,%1,%2,%3}, [%4];" \
        : "=r"((r)[0]), "=r"((r)[1]), "=r"((r)[2]), "=r"((r)[3]) : "r"(a))

#define CP_A16(dst, src) \
    asm volatile("cp.async.cg.shared.global [%0], [%1], 16;" \
                 :: "r"(dst), "l"(src) : "memory")
#define CP_COMMIT() asm volatile("cp.async.commit_group;" ::: "memory")
#define CP_WAIT1()  asm volatile("cp.async.wait_group 1;" ::: "memory")
#define CP_WAIT0()  asm volatile("cp.async.wait_group 0;" ::: "memory")

// ===========================================================================
// fp16 conversion prep (x, w_in, w_out) — one launch
// ===========================================================================
__global__ void toh3(const float* __restrict__ x,  __half* __restrict__ xh,
                     const float* __restrict__ w1, __half* __restrict__ w1h,
                     const float* __restrict__ w2, __half* __restrict__ w2h)
{
    const int nx = MROWS * DD / 4, n1 = N1 * DD / 4, n2 = DD * DD / 4;
    int i = blockIdx.x * blockDim.x + threadIdx.x;
    const float4* s; __half2* d; int j;
    if (i < nx)            { s = (const float4*)x;  d = (__half2*)xh;  j = i; }
    else if (i < nx + n1)  { s = (const float4*)w1; d = (__half2*)w1h; j = i - nx; }
    else if (i < nx + n1 + n2) { s = (const float4*)w2; d = (__half2*)w2h; j = i - nx - n1; }
    else return;
    float4 v = s[j];
    d[2 * j + 0] = __floats2half2_rn(v.x, v.y);
    d[2 * j + 1] = __floats2half2_rn(v.z, v.w);
}

// ===========================================================================
// fp16 mma.sync GEMM: C[M,N] = A[M,K] @ B[N,K]^T + bias[N]
// CTA 128x128, BK=64 halfs (128B rows), 3-stage cp.async, 8 warps (4Mx2N),
// warp tile 32x64, mma.m16n8k16, fp32 accumulate. Stride 72 halfs (144B,
// 144 mod 128 = 16 -> 8-row ldmatrix phases hit distinct bank groups).
// ===========================================================================
#define STAGES  3
#define BKH     64
#define PADH    72
#define TILEH   (128 * PADH)           // halfs per operand tile
#define STAGEH  (2 * TILEH)
#define GSMEM_BYTES (STAGES * STAGEH * 2)   // 110592

template<int OUT_HALF>
__global__ __launch_bounds__(256, 2) void gemm_f16mma(
    const __half* __restrict__ A, const __half* __restrict__ Bm,
    const float* __restrict__ bias, void* __restrict__ Cv,
    int M, int N, int K)
{
    extern __shared__ __half smh[];
    const uint32_t smb = smem_u32(smh);
    const int tid  = threadIdx.x;
    const int lane = tid & 31, wid = tid >> 5;
    const int g = lane >> 2, t = lane & 3;
    const int wm = wid & 3, wn = wid >> 2;
    const int bm = blockIdx.y * 128, bn = blockIdx.x * 128;

    const int lrow = tid >> 3;          // 0..31
    const int lseg = tid & 7;           // 16B segment
    const __half* aBase = A  + (size_t)(bm + lrow) * K + lseg * 8;
    const __half* bBase = Bm + (size_t)(bn + lrow) * K + lseg * 8;
    const uint32_t dA = smb + (uint32_t)((lrow * PADH + lseg * 8) * 2);

    // ldmatrix lane address: row (lane&15), 16B col (lane>>4)
    const uint32_t aAddr0 = smb + (uint32_t)(((wm * 32 + (lane & 15)) * PADH) * 2)
                          + ((lane >> 4) << 4);
    const uint32_t bAddr0 = smb + (uint32_t)((TILEH + (wn * 64 + (lane & 15)) * PADH) * 2)
                          + ((lane >> 4) << 4);

    float acc[2][8][4];
    #pragma unroll
    for (int mt = 0; mt < 2; mt++)
        #pragma unroll
        for (int nt = 0; nt < 8; nt++)
            #pragma unroll
            for (int r = 0; r < 4; r++) acc[mt][nt][r] = 0.f;

#define ISSUE_CHUNK(c, s) do { \
    uint32_t _b = dA + (uint32_t)(s) * (STAGEH * 2); \
    const __half* _pa = aBase + (c) * BKH; \
    const __half* _pb = bBase + (c) * BKH; \
    _Pragma("unroll") \
    for (int _i = 0; _i < 4; _i++) { \
        CP_A16(_b + _i * (32 * PADH * 2),             _pa + (size_t)_i * 32 * K); \
        CP_A16(_b + TILEH * 2 + _i * (32 * PADH * 2), _pb + (size_t)_i * 32 * K); \
    } \
    CP_COMMIT(); \
} while (0)

    const int NCH = K / BKH;   // 16
    ISSUE_CHUNK(0, 0);
    ISSUE_CHUNK(1, 1);

    for (int c = 0; c < NCH; c++) {
        if (c + 1 < NCH) { CP_WAIT1(); } else { CP_WAIT0(); }
        __syncthreads();
        if (c + 2 < NCH) ISSUE_CHUNK(c + 2, (c + 2) % STAGES);
        const uint32_t soff = (uint32_t)((c % STAGES) * (STAGEH * 2));
        #pragma unroll
        for (int ks = 0; ks < 4; ks++) {          // k16 per step
            const uint32_t koff = soff + ks * 32; // 16 halfs
            uint32_t af[2][4], bq[4][4];
            LDSM4(af[0], aAddr0 + koff);
            LDSM4(af[1], aAddr0 + koff + 16 * PADH * 2);
            #pragma unroll
            for (int p = 0; p < 4; p++)
                LDSM4(bq[p], bAddr0 + koff + p * (16 * PADH * 2));
            #pragma unroll
            for (int mt = 0; mt < 2; mt++)
                #pragma unroll
                for (int nt = 0; nt < 8; nt++)
                    MMA_F16(acc[mt][nt],
                            af[mt][0], af[mt][1], af[mt][2], af[mt][3],
                            bq[nt >> 1][nt & 1], bq[nt >> 1][2 + (nt & 1)]);
        }
    }
#undef ISSUE_CHUNK

    const int col0 = bn + wn * 64;
    #pragma unroll
    for (int mt = 0; mt < 2; mt++) {
        #pragma unroll
        for (int h = 0; h < 2; h++) {
            int row = bm + wm * 32 + mt * 16 + g + h * 8;
            #pragma unroll
            for (int nt = 0; nt < 8; nt++) {
                int cc = nt * 8 + t * 2;
                float2 bz = *(const float2*)(bias + col0 + cc);
                float vx = acc[mt][nt][h * 2 + 0] + bz.x;
                float vy = acc[mt][nt][h * 2 + 1] + bz.y;
                if (OUT_HALF) {
                    __half* cp = (__half*)Cv + (size_t)row * N + col0 + cc;
                    *(__half2*)cp = __floats2half2_rn(vx, vy);
                } else {
                    float* cp = (float*)Cv + (size_t)row * N + col0 + cc;
                    *(float2*)cp = make_float2(vx, vy);
                }
            }
        }
    }
}

// ===========================================================================
// fp16 tensor-core flash attention. Block = (128-row q-tile, head, batch),
// 8 warps, warp owns 16 rows. K/V (64 keys) cp.async double-buffered.
// exp2-domain softmax (Q pre-scaled by 0.125*log2e in fp16).
// V fragments via ldmatrix.trans from row-major [key][d].
// ===========================================================================
#define QT  128
#define APD 72                                   // stride (halfs) everywhere
#define AK_OFF(s) (QT * APD + (s) * 64 * APD)
#define AV_OFF(s) (QT * APD + 2 * 64 * APD + (s) * 64 * APD)
#define ASMEM_BYTES ((QT * APD + 4 * 64 * APD) * 2)   // 55296

__global__ __launch_bounds__(256, 2) void flash_attn_f16(const int* __restrict__ causal_flag)
{
    extern __shared__ __half smh[];
    const uint32_t sb = smem_u32(smh);
    __half* Ps = smh;

    const int qt = gridDim.x - 1 - blockIdx.x;   // LPT: heavy CTAs first
    const int h = blockIdx.y, b = blockIdx.z;
    const int tid = threadIdx.x, lane = tid & 31, w = tid >> 5;
    const int g = lane >> 2, t = lane & 3;
    const int causal = *causal_flag;
    const int r0 = w * 16 + g, r1 = r0 + 8;
    const int rowmin = qt * QT + w * 16;

    const int ktmax = causal ? min(2 * qt + 1, SS / 64 - 1) : (SS / 64 - 1);
    const __half* kvb = g_qkv + (size_t)(b * SS) * N1 + DD + h * DH;
    const int irow = tid >> 3;     // 0..31
    const int iseg = tid & 7;

    const uint32_t pAddr = sb + (uint32_t)(((w * 16 + (lane & 15)) * APD) * 2)
                         + ((lane >> 4) << 4);
    const uint32_t kAddr = sb + (uint32_t)((AK_OFF(0) + (lane & 15) * APD) * 2)
                         + ((lane >> 4) << 4);
    const uint32_t vAddr = sb + (uint32_t)((AV_OFF(0) + (lane & 15) * APD) * 2)
                         + ((lane >> 4) << 4);

#define ISSUE_KV(kt, s) do { \
    const __half* _kb = kvb + (size_t)((kt) * 64) * N1; \
    uint32_t _kd = sb + (uint32_t)(AK_OFF(s) * 2); \
    uint32_t _vd = sb + (uint32_t)(AV_OFF(s) * 2); \
    _Pragma("unroll") \
    for (int _i = 0; _i < 2; _i++) { \
        int _r = irow + _i * 32; \
        const __half* _src = _kb + (size_t)_r * N1 + iseg * 8; \
        CP_A16(_kd + (uint32_t)((_r * APD + iseg * 8) * 2), _src); \
        CP_A16(_vd + (uint32_t)((_r * APD + iseg * 8) * 2), _src + DD); \
    } \
    CP_COMMIT(); \
} while (0)

    ISSUE_KV(0, 0);

    // stage Q * (0.125*log2e) in fp16
    {
        const __half2 qs2 = __float2half2_rn(0.125f * 1.4426950408889634f);
        const __half* qb = g_qkv + (size_t)(b * SS + qt * QT) * N1 + h * DH;
        #pragma unroll
        for (int i = 0; i < 4; i++) {
            int fid = tid + i * 256, row = fid >> 3, c8 = fid & 7;
            __half2 v[4];
            *(uint4*)v = *(const uint4*)(qb + (size_t)row * N1 + c8 * 8);
            v[0] = __hmul2(v[0], qs2); v[1] = __hmul2(v[1], qs2);
            v[2] = __hmul2(v[2], qs2); v[3] = __hmul2(v[3], qs2);
            *(uint4*)(Ps + row * APD + c8 * 8) = *(uint4*)v;
        }
    }
    __syncthreads();
    uint32_t qf[4][4];
    #pragma unroll
    for (int ks = 0; ks < 4; ks++) LDSM4(qf[ks], pAddr + ks * 32);

    float m0 = -INFINITY, m1 = -INFINITY, l0 = 0.f, l1 = 0.f;
    float oa[8][4];
    #pragma unroll
    for (int nt = 0; nt < 8; nt++)
        #pragma unroll
        for (int r = 0; r < 4; r++) oa[nt][r] = 0.f;

    for (int kt = 0; kt <= ktmax; kt++) {
        const int cur = kt & 1;
        CP_WAIT0();
        __syncthreads();
        if (kt < ktmax) ISSUE_KV(kt + 1, cur ^ 1);

        if (causal && kt * 64 > rowmin + 15) continue;

        const uint32_t bufK = kAddr + (uint32_t)(cur * (64 * APD * 2));
        const uint32_t bufV = vAddr + (uint32_t)(cur * (64 * APD * 2));

        // ---- S = Q K^T (log2 domain) ----
        float sc[8][4];
        #pragma unroll
        for (int nt = 0; nt < 8; nt++)
            #pragma unroll
            for (int r = 0; r < 4; r++) sc[nt][r] = 0.f;
        #pragma unroll
        for (int ks = 0; ks < 4; ks++) {
            uint32_t kb[4][4];
            #pragma unroll
            for (int p = 0; p < 4; p++)
                LDSM4(kb[p], bufK + ks * 32 + p * (16 * APD * 2));
            #pragma unroll
            for (int nt = 0; nt < 8; nt++)
                MMA_F16(sc[nt], qf[ks][0], qf[ks][1], qf[ks][2], qf[ks][3],
                        kb[nt >> 1][nt & 1], kb[nt >> 1][2 + (nt & 1)]);
        }

        if (causal && kt * 64 + 63 > rowmin) {
            const int r0g = rowmin + g, r1g = r0g + 8;
            #pragma unroll
            for (int nt = 0; nt < 8; nt++) {
                int c0 = kt * 64 + nt * 8 + 2 * t, c1 = c0 + 1;
                if (c0 > r0g) sc[nt][0] = -INFINITY;
                if (c1 > r0g) sc[nt][1] = -INFINITY;
                if (c0 > r1g) sc[nt][2] = -INFINITY;
                if (c1 > r1g) sc[nt][3] = -INFINITY;
            }
        }

        // ---- online softmax (exp2 domain) ----
        float mx0 = m0, mx1 = m1;
        #pragma unroll
        for (int nt = 0; nt < 8; nt++) {
            mx0 = fmaxf(mx0, fmaxf(sc[nt][0], sc[nt][1]));
            mx1 = fmaxf(mx1, fmaxf(sc[nt][2], sc[nt][3]));
        }
        mx0 = fmaxf(mx0, __shfl_xor_sync(0xffffffffu, mx0, 1));
        mx0 = fmaxf(mx0, __shfl_xor_sync(0xffffffffu, mx0, 2));
        mx1 = fmaxf(mx1, __shfl_xor_sync(0xffffffffu, mx1, 1));
        mx1 = fmaxf(mx1, __shfl_xor_sync(0xffffffffu, mx1, 2));
        float a0 = exp2f(m0 - mx0), a1 = exp2f(m1 - mx1);
        m0 = mx0; m1 = mx1;
        l0 *= a0; l1 *= a1;

        float s0 = 0.f, s1 = 0.f;
        #pragma unroll
        for (int nt = 0; nt < 8; nt++) {
            float p00 = exp2f(sc[nt][0] - m0);
            float p01 = exp2f(sc[nt][1] - m0);
            float p10 = exp2f(sc[nt][2] - m1);
            float p11 = exp2f(sc[nt][3] - m1);
            s0 += p00 + p01; s1 += p10 + p11;
            *(__half2*)(Ps + r0 * APD + nt * 8 + 2 * t) = __floats2half2_rn(p00, p01);
            *(__half2*)(Ps + r1 * APD + nt * 8 + 2 * t) = __floats2half2_rn(p10, p11);
            oa[nt][0] *= a0; oa[nt][1] *= a0;
            oa[nt][2] *= a1; oa[nt][3] *= a1;
        }
        s0 += __shfl_xor_sync(0xffffffffu, s0, 1);
        s0 += __shfl_xor_sync(0xffffffffu, s0, 2);
        s1 += __shfl_xor_sync(0xffffffffu, s1, 1);
        s1 += __shfl_xor_sync(0xffffffffu, s1, 2);
        l0 += s0; l1 += s1;
        __syncwarp();

        // ---- O += P V  (V [key][d] row-major; B-frags via ldmatrix.trans) ----
        #pragma unroll
        for (int ks = 0; ks < 4; ks++) {          // key16 per step
            uint32_t pf[4];
            LDSM4(pf, pAddr + ks * 32);
            #pragma unroll
            for (int j = 0; j < 4; j++) {          // d16 blocks
                uint32_t vq[4];
                LDSM4T(vq, bufV + ks * (16 * APD * 2) + j * 32);
                MMA_F16(oa[2 * j + 0], pf[0], pf[1], pf[2], pf[3], vq[0], vq[1]);
                MMA_F16(oa[2 * j + 1], pf[0], pf[1], pf[2], pf[3], vq[2], vq[3]);
            }
        }
        __syncwarp();
    }
#undef ISSUE_KV

    float i0 = 1.f / l0, i1 = 1.f / l1;
    __half* ob = g_att + (size_t)(b * SS + qt * QT) * DD + h * DH;
    #pragma unroll
    for (int nt = 0; nt < 8; nt++) {
        *(__half2*)(ob + (size_t)r0 * DD + nt * 8 + 2 * t) =
            __floats2half2_rn(oa[nt][0] * i0, oa[nt][1] * i0);
        *(__half2*)(ob + (size_t)r1 * DD + nt * 8 + 2 * t) =
            __floats2half2_rn(oa[nt][2] * i1, oa[nt][3] * i1);
    }
}

// ---------------------------------------------------------------------------
extern "C" void kernel_launch(void* const* d_in, const int* in_sizes, int n_in,
                              void* d_out, int out_size)
{
    const float* x     = (const float*)d_in[0];
    const float* w_in  = (const float*)d_in[1];
    const float* b_in  = (const float*)d_in[2];
    const float* w_out = (const float*)d_in[3];
    const float* b_out = (const float*)d_in[4];
    const int*   cmask = (const int*)d_in[5];

    __half *qkv, *att, *xh, *w1h, *w2h;
    cudaGetSymbolAddress((void**)&qkv, g_qkv);
    cudaGetSymbolAddress((void**)&att, g_att);
    cudaGetSymbolAddress((void**)&xh,  g_xh);
    cudaGetSymbolAddress((void**)&w1h, g_w1h);
    cudaGetSymbolAddress((void**)&w2h, g_w2h);

    cudaFuncSetAttribute((const void*)gemm_f16mma<1>,
                         cudaFuncAttributeMaxDynamicSharedMemorySize, GSMEM_BYTES);
    cudaFuncSetAttribute((const void*)gemm_f16mma<0>,
                         cudaFuncAttributeMaxDynamicSharedMemorySize, GSMEM_BYTES);
    cudaFuncSetAttribute((const void*)flash_attn_f16,
                         cudaFuncAttributeMaxDynamicSharedMemorySize, ASMEM_BYTES);

    // 0) convert x, w_in, w_out to fp16 (one launch)
    {
        int tot = MROWS * DD / 4 + N1 * DD / 4 + DD * DD / 4;
        toh3<<<(tot + 255) / 256, 256>>>(x, xh, w_in, w1h, w_out, w2h);
    }

    // 1) QKV projection -> fp16 qkv
    gemm_f16mma<1><<<dim3(N1 / 128, MROWS / 128), 256, GSMEM_BYTES>>>(
        xh, w1h, b_in, qkv, MROWS, N1, DD);

    // 2) Causal multi-head flash attention (fp16 tensor cores)
    flash_attn_f16<<<dim3(SS / QT, HH, BB), 256, ASMEM_BYTES>>>(cmask);

    // 3) Output projection -> fp32 out
    gemm_f16mma<0><<<dim3(DD / 128, MROWS / 128), 256, GSMEM_BYTES>>>(
        att, w2h, b_out, (float*)d_out, MROWS, DD, DD);
}

// round 10
// speedup vs baseline: 1.7718x; 1.0298x over previous
#include <cuda_runtime.h>
#include <cuda_fp16.h>
#include <math.h>
#include <stdint.h>

// Problem constants
#define BB 4
#define SS 2048
#define DD 1024
#define HH 16
#define DH 64
#define MROWS (BB * SS)      // 8192
#define N1 (3 * DD)          // 3072

// Scratch (allocation-free: device globals), all fp16 inter-stage
__device__ __half g_qkv[(size_t)MROWS * N1];   // [B*S, 3D]
__device__ __half g_att[(size_t)MROWS * DD];   // [B*S, D]
__device__ __half g_xh [(size_t)MROWS * DD];
__device__ __half g_w1h[(size_t)N1 * DD];
__device__ __half g_w2h[(size_t)DD * DD];

// ===========================================================================
// helpers
// ===========================================================================
__device__ __forceinline__ uint32_t smem_u32(const void* p) {
    uint32_t a;
    asm("{ .reg .u64 t; cvta.to.shared.u64 t, %1; cvt.u32.u64 %0, t; }"
        : "=r"(a) : "l"(p));
    return a;
}
__device__ __forceinline__ uint32_t packh2(float a, float b) {
    __half2 h = __floats2half2_rn(a, b);
    return *reinterpret_cast<uint32_t*>(&h);
}

#define MMA_F16(acc, a0, a1, a2, a3, b0, b1) \
    asm volatile( \
        "mma.sync.aligned.m16n8k16.row.col.f32.f16.f16.f32 " \
        "{%0,%1,%2,%3}, {%4,%5,%6,%7}, {%8,%9}, {%0,%1,%2,%3};" \
        : "+f"((acc)[0]), "+f"((acc)[1]), "+f"((acc)[2]), "+f"((acc)[3]) \
        : "r"(a0), "r"(a1), "r"(a2), "r"(a3), "r"(b0), "r"(b1))

#define LDSM4(r, a) \
    asm volatile("ldmatrix.sync.aligned.m8n8.x4.shared.b16 {%0,%1,%2,%3}, [%4];" \
        : "=r"((r)[0]), "=r"((r)[1]), "=r"((r)[2]), "=r"((r)[3]) : "r"(a))
#define LDSM4T(r, a) \
    asm volatile("ldmatrix.sync.aligned.m8n8.x4.trans.shared.b16 {%0,%1,%2,%3}, [%4];" \
        : "=r"((r)[0]), "=r"((r)[1]), "=r"((r)[2]), "=r"((r)[3]) : "r"(a))

#define CP_A16(dst, src) \
    asm volatile("cp.async.cg.shared.global [%0], [%1], 16;" \
                 :: "r"(dst), "l"(src) : "memory")
#define CP_COMMIT() asm volatile("cp.async.commit_group;" ::: "memory")
#define CP_WAIT1()  asm volatile("cp.async.wait_group 1;" ::: "memory")
#define CP_WAIT0()  asm volatile("cp.async.wait_group 0;" ::: "memory")

// ===========================================================================
// fp16 conversion prep (x, w_in, w_out) — one launch
// ===========================================================================
__global__ void toh3(const float* __restrict__ x,  __half* __restrict__ xh,
                     const float* __restrict__ w1, __half* __restrict__ w1h,
                     const float* __restrict__ w2, __half* __restrict__ w2h)
{
    const int nx = MROWS * DD / 4, n1 = N1 * DD / 4, n2 = DD * DD / 4;
    int i = blockIdx.x * blockDim.x + threadIdx.x;
    const float4* s; __half2* d; int j;
    if (i < nx)            { s = (const float4*)x;  d = (__half2*)xh;  j = i; }
    else if (i < nx + n1)  { s = (const float4*)w1; d = (__half2*)w1h; j = i - nx; }
    else if (i < nx + n1 + n2) { s = (const float4*)w2; d = (__half2*)w2h; j = i - nx - n1; }
    else return;
    float4 v = s[j];
    d[2 * j + 0] = __floats2half2_rn(v.x, v.y);
    d[2 * j + 1] = __floats2half2_rn(v.z, v.w);
}

// ===========================================================================
// fp16 mma.sync GEMM: C[M,N] = A[M,K] @ B[N,K]^T + bias[N]
// CTA 128x128, BK=64 halfs, 3-stage cp.async, 8 warps (4Mx2N),
// warp tile 32x64, mma.m16n8k16, fp32 accumulate. (UNCHANGED from R8.)
// ===========================================================================
#define STAGES  3
#define BKH     64
#define PADH    72
#define TILEH   (128 * PADH)
#define STAGEH  (2 * TILEH)
#define GSMEM_BYTES (STAGES * STAGEH * 2)   // 110592

template<int OUT_HALF>
__global__ __launch_bounds__(256, 2) void gemm_f16mma(
    const __half* __restrict__ A, const __half* __restrict__ Bm,
    const float* __restrict__ bias, void* __restrict__ Cv,
    int M, int N, int K)
{
    extern __shared__ __half smh[];
    const uint32_t smb = smem_u32(smh);
    const int tid  = threadIdx.x;
    const int lane = tid & 31, wid = tid >> 5;
    const int g = lane >> 2, t = lane & 3;
    const int wm = wid & 3, wn = wid >> 2;
    const int bm = blockIdx.y * 128, bn = blockIdx.x * 128;

    const int lrow = tid >> 3;
    const int lseg = tid & 7;
    const __half* aBase = A  + (size_t)(bm + lrow) * K + lseg * 8;
    const __half* bBase = Bm + (size_t)(bn + lrow) * K + lseg * 8;
    const uint32_t dA = smb + (uint32_t)((lrow * PADH + lseg * 8) * 2);

    const uint32_t aAddr0 = smb + (uint32_t)(((wm * 32 + (lane & 15)) * PADH) * 2)
                          + ((lane >> 4) << 4);
    const uint32_t bAddr0 = smb + (uint32_t)((TILEH + (wn * 64 + (lane & 15)) * PADH) * 2)
                          + ((lane >> 4) << 4);

    float acc[2][8][4];
    #pragma unroll
    for (int mt = 0; mt < 2; mt++)
        #pragma unroll
        for (int nt = 0; nt < 8; nt++)
            #pragma unroll
            for (int r = 0; r < 4; r++) acc[mt][nt][r] = 0.f;

#define ISSUE_CHUNK(c, s) do { \
    uint32_t _b = dA + (uint32_t)(s) * (STAGEH * 2); \
    const __half* _pa = aBase + (c) * BKH; \
    const __half* _pb = bBase + (c) * BKH; \
    _Pragma("unroll") \
    for (int _i = 0; _i < 4; _i++) { \
        CP_A16(_b + _i * (32 * PADH * 2),             _pa + (size_t)_i * 32 * K); \
        CP_A16(_b + TILEH * 2 + _i * (32 * PADH * 2), _pb + (size_t)_i * 32 * K); \
    } \
    CP_COMMIT(); \
} while (0)

    const int NCH = K / BKH;
    ISSUE_CHUNK(0, 0);
    ISSUE_CHUNK(1, 1);

    for (int c = 0; c < NCH; c++) {
        if (c + 1 < NCH) { CP_WAIT1(); } else { CP_WAIT0(); }
        __syncthreads();
        if (c + 2 < NCH) ISSUE_CHUNK(c + 2, (c + 2) % STAGES);
        const uint32_t soff = (uint32_t)((c % STAGES) * (STAGEH * 2));
        #pragma unroll
        for (int ks = 0; ks < 4; ks++) {
            const uint32_t koff = soff + ks * 32;
            uint32_t af[2][4], bq[4][4];
            LDSM4(af[0], aAddr0 + koff);
            LDSM4(af[1], aAddr0 + koff + 16 * PADH * 2);
            #pragma unroll
            for (int p = 0; p < 4; p++)
                LDSM4(bq[p], bAddr0 + koff + p * (16 * PADH * 2));
            #pragma unroll
            for (int mt = 0; mt < 2; mt++)
                #pragma unroll
                for (int nt = 0; nt < 8; nt++)
                    MMA_F16(acc[mt][nt],
                            af[mt][0], af[mt][1], af[mt][2], af[mt][3],
                            bq[nt >> 1][nt & 1], bq[nt >> 1][2 + (nt & 1)]);
        }
    }
#undef ISSUE_CHUNK

    const int col0 = bn + wn * 64;
    #pragma unroll
    for (int mt = 0; mt < 2; mt++) {
        #pragma unroll
        for (int h = 0; h < 2; h++) {
            int row = bm + wm * 32 + mt * 16 + g + h * 8;
            #pragma unroll
            for (int nt = 0; nt < 8; nt++) {
                int cc = nt * 8 + t * 2;
                float2 bz = *(const float2*)(bias + col0 + cc);
                float vx = acc[mt][nt][h * 2 + 0] + bz.x;
                float vy = acc[mt][nt][h * 2 + 1] + bz.y;
                if (OUT_HALF) {
                    __half* cp = (__half*)Cv + (size_t)row * N + col0 + cc;
                    *(__half2*)cp = __floats2half2_rn(vx, vy);
                } else {
                    float* cp = (float*)Cv + (size_t)row * N + col0 + cc;
                    *(float2*)cp = make_float2(vx, vy);
                }
            }
        }
    }
}

// ===========================================================================
// fp16 tensor-core flash attention. Block = (128-row q-tile, head, batch),
// 8 warps, warp owns 16 rows. K/V (64 keys) cp.async double-buffered.
// exp2-domain softmax. NEW: P accumulator -> PV A-fragment by direct per-lane
// register repack (no smem round-trip, no syncwarp); l kept lane-partial and
// reduced once at the end.
// ===========================================================================
#define QT  128
#define APD 72
#define AK_OFF(s) (QT * APD + (s) * 64 * APD)
#define AV_OFF(s) (QT * APD + 2 * 64 * APD + (s) * 64 * APD)
#define ASMEM_BYTES ((QT * APD + 4 * 64 * APD) * 2)   // 55296

__global__ __launch_bounds__(256, 2) void flash_attn_f16(const int* __restrict__ causal_flag)
{
    extern __shared__ __half smh[];
    const uint32_t sb = smem_u32(smh);
    __half* Ps = smh;   // Q staging only

    const int qt = gridDim.x - 1 - blockIdx.x;   // LPT: heavy CTAs first
    const int h = blockIdx.y, b = blockIdx.z;
    const int tid = threadIdx.x, lane = tid & 31, w = tid >> 5;
    const int g = lane >> 2, t = lane & 3;
    const int causal = *causal_flag;
    const int r0 = w * 16 + g, r1 = r0 + 8;
    const int rowmin = qt * QT + w * 16;

    const int ktmax = causal ? min(2 * qt + 1, SS / 64 - 1) : (SS / 64 - 1);
    const __half* kvb = g_qkv + (size_t)(b * SS) * N1 + DD + h * DH;
    const int irow = tid >> 3;
    const int iseg = tid & 7;

    const uint32_t pAddr = sb + (uint32_t)(((w * 16 + (lane & 15)) * APD) * 2)
                         + ((lane >> 4) << 4);
    const uint32_t kAddr = sb + (uint32_t)((AK_OFF(0) + (lane & 15) * APD) * 2)
                         + ((lane >> 4) << 4);
    const uint32_t vAddr = sb + (uint32_t)((AV_OFF(0) + (lane & 15) * APD) * 2)
                         + ((lane >> 4) << 4);

#define ISSUE_KV(kt, s) do { \
    const __half* _kb = kvb + (size_t)((kt) * 64) * N1; \
    uint32_t _kd = sb + (uint32_t)(AK_OFF(s) * 2); \
    uint32_t _vd = sb + (uint32_t)(AV_OFF(s) * 2); \
    _Pragma("unroll") \
    for (int _i = 0; _i < 2; _i++) { \
        int _r = irow + _i * 32; \
        const __half* _src = _kb + (size_t)_r * N1 + iseg * 8; \
        CP_A16(_kd + (uint32_t)((_r * APD + iseg * 8) * 2), _src); \
        CP_A16(_vd + (uint32_t)((_r * APD + iseg * 8) * 2), _src + DD); \
    } \
    CP_COMMIT(); \
} while (0)

    ISSUE_KV(0, 0);

    // stage Q * (0.125*log2e) in fp16
    {
        const __half2 qs2 = __float2half2_rn(0.125f * 1.4426950408889634f);
        const __half* qb = g_qkv + (size_t)(b * SS + qt * QT) * N1 + h * DH;
        #pragma unroll
        for (int i = 0; i < 4; i++) {
            int fid = tid + i * 256, row = fid >> 3, c8 = fid & 7;
            __half2 v[4];
            *(uint4*)v = *(const uint4*)(qb + (size_t)row * N1 + c8 * 8);
            v[0] = __hmul2(v[0], qs2); v[1] = __hmul2(v[1], qs2);
            v[2] = __hmul2(v[2], qs2); v[3] = __hmul2(v[3], qs2);
            *(uint4*)(Ps + row * APD + c8 * 8) = *(uint4*)v;
        }
    }
    __syncthreads();
    uint32_t qf[4][4];
    #pragma unroll
    for (int ks = 0; ks < 4; ks++) LDSM4(qf[ks], pAddr + ks * 32);

    float m0 = -INFINITY, m1 = -INFINITY;
    float l0 = 0.f, l1 = 0.f;            // LANE-PARTIAL row sums
    float oa[8][4];
    #pragma unroll
    for (int nt = 0; nt < 8; nt++)
        #pragma unroll
        for (int r = 0; r < 4; r++) oa[nt][r] = 0.f;

    for (int kt = 0; kt <= ktmax; kt++) {
        const int cur = kt & 1;
        CP_WAIT0();
        __syncthreads();
        if (kt < ktmax) ISSUE_KV(kt + 1, cur ^ 1);

        if (causal && kt * 64 > rowmin + 15) continue;

        const uint32_t bufK = kAddr + (uint32_t)(cur * (64 * APD * 2));
        const uint32_t bufV = vAddr + (uint32_t)(cur * (64 * APD * 2));

        // ---- S = Q K^T (log2 domain) ----
        float sc[8][4];
        #pragma unroll
        for (int nt = 0; nt < 8; nt++)
            #pragma unroll
            for (int r = 0; r < 4; r++) sc[nt][r] = 0.f;
        #pragma unroll
        for (int ks = 0; ks < 4; ks++) {
            uint32_t kb[4][4];
            #pragma unroll
            for (int p = 0; p < 4; p++)
                LDSM4(kb[p], bufK + ks * 32 + p * (16 * APD * 2));
            #pragma unroll
            for (int nt = 0; nt < 8; nt++)
                MMA_F16(sc[nt], qf[ks][0], qf[ks][1], qf[ks][2], qf[ks][3],
                        kb[nt >> 1][nt & 1], kb[nt >> 1][2 + (nt & 1)]);
        }

        if (causal && kt * 64 + 63 > rowmin) {
            const int r0g = rowmin + g, r1g = r0g + 8;
            #pragma unroll
            for (int nt = 0; nt < 8; nt++) {
                int c0 = kt * 64 + nt * 8 + 2 * t, c1 = c0 + 1;
                if (c0 > r0g) sc[nt][0] = -INFINITY;
                if (c1 > r0g) sc[nt][1] = -INFINITY;
                if (c0 > r1g) sc[nt][2] = -INFINITY;
                if (c1 > r1g) sc[nt][3] = -INFINITY;
            }
        }

        // ---- online softmax (exp2 domain); P packed directly to fragments ----
        float mx0 = m0, mx1 = m1;
        #pragma unroll
        for (int nt = 0; nt < 8; nt++) {
            mx0 = fmaxf(mx0, fmaxf(sc[nt][0], sc[nt][1]));
            mx1 = fmaxf(mx1, fmaxf(sc[nt][2], sc[nt][3]));
        }
        mx0 = fmaxf(mx0, __shfl_xor_sync(0xffffffffu, mx0, 1));
        mx0 = fmaxf(mx0, __shfl_xor_sync(0xffffffffu, mx0, 2));
        mx1 = fmaxf(mx1, __shfl_xor_sync(0xffffffffu, mx1, 1));
        mx1 = fmaxf(mx1, __shfl_xor_sync(0xffffffffu, mx1, 2));
        float a0 = exp2f(m0 - mx0), a1 = exp2f(m1 - mx1);
        m0 = mx0; m1 = mx1;

        float s0 = 0.f, s1 = 0.f;
        uint32_t ph[8][2];                 // P in A-fragment packing
        #pragma unroll
        for (int nt = 0; nt < 8; nt++) {
            float p00 = exp2f(sc[nt][0] - m0);
            float p01 = exp2f(sc[nt][1] - m0);
            float p10 = exp2f(sc[nt][2] - m1);
            float p11 = exp2f(sc[nt][3] - m1);
            s0 += p00 + p01; s1 += p10 + p11;
            ph[nt][0] = packh2(p00, p01);  // row g   pair
            ph[nt][1] = packh2(p10, p11);  // row g+8 pair
            oa[nt][0] *= a0; oa[nt][1] *= a0;
            oa[nt][2] *= a1; oa[nt][3] *= a1;
        }
        l0 = l0 * a0 + s0;                 // lane-partial; reduced at the end
        l1 = l1 * a1 + s1;

        // ---- O += P V  (V [key][d]; B-frags via ldmatrix.trans) ----
        #pragma unroll
        for (int ks = 0; ks < 4; ks++) {   // key16 block
            const uint32_t pf0 = ph[2 * ks][0],     pf1 = ph[2 * ks][1];
            const uint32_t pf2 = ph[2 * ks + 1][0], pf3 = ph[2 * ks + 1][1];
            #pragma unroll
            for (int j = 0; j < 4; j++) {  // d16 blocks
                uint32_t vq[4];
                LDSM4T(vq, bufV + ks * (16 * APD * 2) + j * 32);
                MMA_F16(oa[2 * j + 0], pf0, pf1, pf2, pf3, vq[0], vq[1]);
                MMA_F16(oa[2 * j + 1], pf0, pf1, pf2, pf3, vq[2], vq[3]);
            }
        }
    }
#undef ISSUE_KV

    // final cross-quad reduction of lane-partial row sums
    l0 += __shfl_xor_sync(0xffffffffu, l0, 1);
    l0 += __shfl_xor_sync(0xffffffffu, l0, 2);
    l1 += __shfl_xor_sync(0xffffffffu, l1, 1);
    l1 += __shfl_xor_sync(0xffffffffu, l1, 2);

    float i0 = 1.f / l0, i1 = 1.f / l1;
    __half* ob = g_att + (size_t)(b * SS + qt * QT) * DD + h * DH;
    #pragma unroll
    for (int nt = 0; nt < 8; nt++) {
        *(__half2*)(ob + (size_t)r0 * DD + nt * 8 + 2 * t) =
            __floats2half2_rn(oa[nt][0] * i0, oa[nt][1] * i0);
        *(__half2*)(ob + (size_t)r1 * DD + nt * 8 + 2 * t) =
            __floats2half2_rn(oa[nt][2] * i1, oa[nt][3] * i1);
    }
}

// ---------------------------------------------------------------------------
extern "C" void kernel_launch(void* const* d_in, const int* in_sizes, int n_in,
                              void* d_out, int out_size)
{
    const float* x     = (const float*)d_in[0];
    const float* w_in  = (const float*)d_in[1];
    const float* b_in  = (const float*)d_in[2];
    const float* w_out = (const float*)d_in[3];
    const float* b_out = (const float*)d_in[4];
    const int*   cmask = (const int*)d_in[5];

    __half *qkv, *att, *xh, *w1h, *w2h;
    cudaGetSymbolAddress((void**)&qkv, g_qkv);
    cudaGetSymbolAddress((void**)&att, g_att);
    cudaGetSymbolAddress((void**)&xh,  g_xh);
    cudaGetSymbolAddress((void**)&w1h, g_w1h);
    cudaGetSymbolAddress((void**)&w2h, g_w2h);

    cudaFuncSetAttribute((const void*)gemm_f16mma<1>,
                         cudaFuncAttributeMaxDynamicSharedMemorySize, GSMEM_BYTES);
    cudaFuncSetAttribute((const void*)gemm_f16mma<0>,
                         cudaFuncAttributeMaxDynamicSharedMemorySize, GSMEM_BYTES);
    cudaFuncSetAttribute((const void*)flash_attn_f16,
                         cudaFuncAttributeMaxDynamicSharedMemorySize, ASMEM_BYTES);

    // 0) convert x, w_in, w_out to fp16 (one launch)
    {
        int tot = MROWS * DD / 4 + N1 * DD / 4 + DD * DD / 4;
        toh3<<<(tot + 255) / 256, 256>>>(x, xh, w_in, w1h, w_out, w2h);
    }

    // 1) QKV projection -> fp16 qkv
    gemm_f16mma<1><<<dim3(N1 / 128, MROWS / 128), 256, GSMEM_BYTES>>>(
        xh, w1h, b_in, qkv, MROWS, N1, DD);

    // 2) Causal multi-head flash attention (fp16 tensor cores, reg-repacked P)
    flash_attn_f16<<<dim3(SS / QT, HH, BB), 256, ASMEM_BYTES>>>(cmask);

    // 3) Output projection -> fp32 out
    gemm_f16mma<0><<<dim3(DD / 128, MROWS / 128), 256, GSMEM_BYTES>>>(
        att, w2h, b_out, (float*)d_out, MROWS, DD, DD);
}

// round 11
// speedup vs baseline: 1.7817x; 1.0056x over previous
#include <cuda_runtime.h>
#include <cuda_fp16.h>
#include <math.h>
#include <stdint.h>

// Problem constants
#define BB 4
#define SS 2048
#define DD 1024
#define HH 16
#define DH 64
#define MROWS (BB * SS)      // 8192
#define N1 (3 * DD)          // 3072

// Scratch (allocation-free: device globals), all fp16 inter-stage
__device__ __half g_qkv[(size_t)MROWS * N1];   // [B*S, 3D]
__device__ __half g_att[(size_t)MROWS * DD];   // [B*S, D]
__device__ __half g_xh [(size_t)MROWS * DD];
__device__ __half g_w1h[(size_t)N1 * DD];
__device__ __half g_w2h[(size_t)DD * DD];

// ===========================================================================
// helpers
// ===========================================================================
__device__ __forceinline__ uint32_t smem_u32(const void* p) {
    uint32_t a;
    asm("{ .reg .u64 t; cvta.to.shared.u64 t, %1; cvt.u32.u64 %0, t; }"
        : "=r"(a) : "l"(p));
    return a;
}
__device__ __forceinline__ uint32_t packh2(float a, float b) {
    __half2 h = __floats2half2_rn(a, b);
    return *reinterpret_cast<uint32_t*>(&h);
}

#define MMA_F16(acc, a0, a1, a2, a3, b0, b1) \
    asm volatile( \
        "mma.sync.aligned.m16n8k16.row.col.f32.f16.f16.f32 " \
        "{%0,%1,%2,%3}, {%4,%5,%6,%7}, {%8,%9}, {%0,%1,%2,%3};" \
        : "+f"((acc)[0]), "+f"((acc)[1]), "+f"((acc)[2]), "+f"((acc)[3]) \
        : "r"(a0), "r"(a1), "r"(a2), "r"(a3), "r"(b0), "r"(b1))

#define LDSM4(r, a) \
    asm volatile("ldmatrix.sync.aligned.m8n8.x4.shared.b16 {%0,%1,%2,%3}, [%4];" \
        : "=r"((r)[0]), "=r"((r)[1]), "=r"((r)[2]), "=r"((r)[3]) : "r"(a))
#define LDSM4T(r, a) \
    asm volatile("ldmatrix.sync.aligned.m8n8.x4.trans.shared.b16 {%0,%1,%2,%3}, [%4];" \
        : "=r"((r)[0]), "=r"((r)[1]), "=r"((r)[2]), "=r"((r)[3]) : "r"(a))

#define CP_A16(dst, src) \
    asm volatile("cp.async.cg.shared.global [%0], [%1], 16;" \
                 :: "r"(dst), "l"(src) : "memory")
#define CP_COMMIT() asm volatile("cp.async.commit_group;" ::: "memory")
#define CP_WAIT1()  asm volatile("cp.async.wait_group 1;" ::: "memory")
#define CP_WAIT0()  asm volatile("cp.async.wait_group 0;" ::: "memory")

// ===========================================================================
// fp16 conversion prep (x, w_in, w_out) — one launch
// ===========================================================================
__global__ void toh3(const float* __restrict__ x,  __half* __restrict__ xh,
                     const float* __restrict__ w1, __half* __restrict__ w1h,
                     const float* __restrict__ w2, __half* __restrict__ w2h)
{
    const int nx = MROWS * DD / 4, n1 = N1 * DD / 4, n2 = DD * DD / 4;
    int i = blockIdx.x * blockDim.x + threadIdx.x;
    const float4* s; __half2* d; int j;
    if (i < nx)            { s = (const float4*)x;  d = (__half2*)xh;  j = i; }
    else if (i < nx + n1)  { s = (const float4*)w1; d = (__half2*)w1h; j = i - nx; }
    else if (i < nx + n1 + n2) { s = (const float4*)w2; d = (__half2*)w2h; j = i - nx - n1; }
    else return;
    float4 v = s[j];
    d[2 * j + 0] = __floats2half2_rn(v.x, v.y);
    d[2 * j + 1] = __floats2half2_rn(v.z, v.w);
}

// ===========================================================================
// fp16 mma.sync GEMM: C[M,N] = A[M,K] @ B[N,K]^T + bias[N]
// CTA 128x128, BK=64 halfs, 3-stage cp.async, 8 warps (4Mx2N),
// warp tile 32x64, mma.m16n8k16, fp32 accumulate.
// NEW: per-warp ks-phase stagger (wid&3) to break lockstep LDSM/MMA phases.
// ===========================================================================
#define STAGES  3
#define BKH     64
#define PADH    72
#define TILEH   (128 * PADH)
#define STAGEH  (2 * TILEH)
#define GSMEM_BYTES (STAGES * STAGEH * 2)   // 110592

template<int OUT_HALF>
__global__ __launch_bounds__(256, 2) void gemm_f16mma(
    const __half* __restrict__ A, const __half* __restrict__ Bm,
    const float* __restrict__ bias, void* __restrict__ Cv,
    int M, int N, int K)
{
    extern __shared__ __half smh[];
    const uint32_t smb = smem_u32(smh);
    const int tid  = threadIdx.x;
    const int lane = tid & 31, wid = tid >> 5;
    const int g = lane >> 2, t = lane & 3;
    const int wm = wid & 3, wn = wid >> 2;
    const int kphase = wid & 3;          // stagger phase
    const int bm = blockIdx.y * 128, bn = blockIdx.x * 128;

    const int lrow = tid >> 3;
    const int lseg = tid & 7;
    const __half* aBase = A  + (size_t)(bm + lrow) * K + lseg * 8;
    const __half* bBase = Bm + (size_t)(bn + lrow) * K + lseg * 8;
    const uint32_t dA = smb + (uint32_t)((lrow * PADH + lseg * 8) * 2);

    const uint32_t aAddr0 = smb + (uint32_t)(((wm * 32 + (lane & 15)) * PADH) * 2)
                          + ((lane >> 4) << 4);
    const uint32_t bAddr0 = smb + (uint32_t)((TILEH + (wn * 64 + (lane & 15)) * PADH) * 2)
                          + ((lane >> 4) << 4);

    float acc[2][8][4];
    #pragma unroll
    for (int mt = 0; mt < 2; mt++)
        #pragma unroll
        for (int nt = 0; nt < 8; nt++)
            #pragma unroll
            for (int r = 0; r < 4; r++) acc[mt][nt][r] = 0.f;

#define ISSUE_CHUNK(c, s) do { \
    uint32_t _b = dA + (uint32_t)(s) * (STAGEH * 2); \
    const __half* _pa = aBase + (c) * BKH; \
    const __half* _pb = bBase + (c) * BKH; \
    _Pragma("unroll") \
    for (int _i = 0; _i < 4; _i++) { \
        CP_A16(_b + _i * (32 * PADH * 2),             _pa + (size_t)_i * 32 * K); \
        CP_A16(_b + TILEH * 2 + _i * (32 * PADH * 2), _pb + (size_t)_i * 32 * K); \
    } \
    CP_COMMIT(); \
} while (0)

    const int NCH = K / BKH;
    ISSUE_CHUNK(0, 0);
    ISSUE_CHUNK(1, 1);

    for (int c = 0; c < NCH; c++) {
        if (c + 1 < NCH) { CP_WAIT1(); } else { CP_WAIT0(); }
        __syncthreads();
        if (c + 2 < NCH) ISSUE_CHUNK(c + 2, (c + 2) % STAGES);
        const uint32_t soff = (uint32_t)((c % STAGES) * (STAGEH * 2));
        #pragma unroll
        for (int s = 0; s < 4; s++) {
            const int ks = (s + kphase) & 3;     // staggered step order
            const uint32_t koff = soff + ks * 32;
            uint32_t af[2][4], bq[4][4];
            LDSM4(af[0], aAddr0 + koff);
            LDSM4(af[1], aAddr0 + koff + 16 * PADH * 2);
            #pragma unroll
            for (int p = 0; p < 4; p++)
                LDSM4(bq[p], bAddr0 + koff + p * (16 * PADH * 2));
            #pragma unroll
            for (int mt = 0; mt < 2; mt++)
                #pragma unroll
                for (int nt = 0; nt < 8; nt++)
                    MMA_F16(acc[mt][nt],
                            af[mt][0], af[mt][1], af[mt][2], af[mt][3],
                            bq[nt >> 1][nt & 1], bq[nt >> 1][2 + (nt & 1)]);
        }
    }
#undef ISSUE_CHUNK

    const int col0 = bn + wn * 64;
    #pragma unroll
    for (int mt = 0; mt < 2; mt++) {
        #pragma unroll
        for (int h = 0; h < 2; h++) {
            int row = bm + wm * 32 + mt * 16 + g + h * 8;
            #pragma unroll
            for (int nt = 0; nt < 8; nt++) {
                int cc = nt * 8 + t * 2;
                float2 bz = *(const float2*)(bias + col0 + cc);
                float vx = acc[mt][nt][h * 2 + 0] + bz.x;
                float vy = acc[mt][nt][h * 2 + 1] + bz.y;
                if (OUT_HALF) {
                    __half* cp = (__half*)Cv + (size_t)row * N + col0 + cc;
                    *(__half2*)cp = __floats2half2_rn(vx, vy);
                } else {
                    float* cp = (float*)Cv + (size_t)row * N + col0 + cc;
                    *(float2*)cp = make_float2(vx, vy);
                }
            }
        }
    }
}

// ===========================================================================
// fp16 tensor-core flash attention. Block = (128-row q-tile, head, batch),
// 8 warps, warp owns 16 rows. NEW: 128-key load tiles (double-buffered),
// processed as two 64-key halves (same registers) -> half the barrier count.
// exp2-domain softmax, P register-repacked to PV A-fragments.
// ===========================================================================
#define QT  128
#define KT2 128                          // keys per load tile
#define APD 72
#define AK_OFF(s) (QT * APD + (s) * KT2 * APD)
#define AV_OFF(s) (QT * APD + 2 * KT2 * APD + (s) * KT2 * APD)
#define ASMEM_BYTES ((QT * APD + 4 * KT2 * APD) * 2)   // 92160

__global__ __launch_bounds__(256, 2) void flash_attn_f16(const int* __restrict__ causal_flag)
{
    extern __shared__ __half smh[];
    const uint32_t sb = smem_u32(smh);
    __half* Ps = smh;   // Q staging only

    const int qt = gridDim.x - 1 - blockIdx.x;   // LPT: heavy CTAs first
    const int h = blockIdx.y, b = blockIdx.z;
    const int tid = threadIdx.x, lane = tid & 31, w = tid >> 5;
    const int g = lane >> 2, t = lane & 3;
    const int causal = *causal_flag;
    const int r0 = w * 16 + g, r1 = r0 + 8;
    const int rowmin = qt * QT + w * 16;

    // 128-key tiles: diagonal tile index == qt (since QT == KT2)
    const int ktmax = causal ? qt : (SS / KT2 - 1);
    const __half* kvb = g_qkv + (size_t)(b * SS) * N1 + DD + h * DH;
    const int irow = tid >> 3;     // 0..31
    const int iseg = tid & 7;

    const uint32_t pAddr = sb + (uint32_t)(((w * 16 + (lane & 15)) * APD) * 2)
                         + ((lane >> 4) << 4);
    const uint32_t kAddr = sb + (uint32_t)((AK_OFF(0) + (lane & 15) * APD) * 2)
                         + ((lane >> 4) << 4);
    const uint32_t vAddr = sb + (uint32_t)((AV_OFF(0) + (lane & 15) * APD) * 2)
                         + ((lane >> 4) << 4);

#define ISSUE_KV(kt, s) do { \
    const __half* _kb = kvb + (size_t)((kt) * KT2) * N1; \
    uint32_t _kd = sb + (uint32_t)(AK_OFF(s) * 2); \
    uint32_t _vd = sb + (uint32_t)(AV_OFF(s) * 2); \
    _Pragma("unroll") \
    for (int _i = 0; _i < 4; _i++) { \
        int _r = irow + _i * 32; \
        const __half* _src = _kb + (size_t)_r * N1 + iseg * 8; \
        CP_A16(_kd + (uint32_t)((_r * APD + iseg * 8) * 2), _src); \
        CP_A16(_vd + (uint32_t)((_r * APD + iseg * 8) * 2), _src + DD); \
    } \
    CP_COMMIT(); \
} while (0)

    ISSUE_KV(0, 0);

    // stage Q * (0.125*log2e) in fp16
    {
        const __half2 qs2 = __float2half2_rn(0.125f * 1.4426950408889634f);
        const __half* qb = g_qkv + (size_t)(b * SS + qt * QT) * N1 + h * DH;
        #pragma unroll
        for (int i = 0; i < 4; i++) {
            int fid = tid + i * 256, row = fid >> 3, c8 = fid & 7;
            __half2 v[4];
            *(uint4*)v = *(const uint4*)(qb + (size_t)row * N1 + c8 * 8);
            v[0] = __hmul2(v[0], qs2); v[1] = __hmul2(v[1], qs2);
            v[2] = __hmul2(v[2], qs2); v[3] = __hmul2(v[3], qs2);
            *(uint4*)(Ps + row * APD + c8 * 8) = *(uint4*)v;
        }
    }
    __syncthreads();
    uint32_t qf[4][4];
    #pragma unroll
    for (int ks = 0; ks < 4; ks++) LDSM4(qf[ks], pAddr + ks * 32);

    float m0 = -INFINITY, m1 = -INFINITY;
    float l0 = 0.f, l1 = 0.f;            // lane-partial row sums
    float oa[8][4];
    #pragma unroll
    for (int nt = 0; nt < 8; nt++)
        #pragma unroll
        for (int r = 0; r < 4; r++) oa[nt][r] = 0.f;

    for (int kt = 0; kt <= ktmax; kt++) {
        const int cur = kt & 1;
        CP_WAIT0();
        __syncthreads();
        if (kt < ktmax) ISSUE_KV(kt + 1, cur ^ 1);

        const uint32_t tileK = kAddr + (uint32_t)(cur * (KT2 * APD * 2));
        const uint32_t tileV = vAddr + (uint32_t)(cur * (KT2 * APD * 2));

        #pragma unroll
        for (int half = 0; half < 2; half++) {
            const int keybase = kt * KT2 + half * 64;
            if (causal && keybase > rowmin + 15) continue;   // warp skip

            const uint32_t bufK = tileK + (uint32_t)(half * (64 * APD * 2));
            const uint32_t bufV = tileV + (uint32_t)(half * (64 * APD * 2));

            // ---- S = Q K^T (log2 domain) ----
            float sc[8][4];
            #pragma unroll
            for (int nt = 0; nt < 8; nt++)
                #pragma unroll
                for (int r = 0; r < 4; r++) sc[nt][r] = 0.f;
            #pragma unroll
            for (int ks = 0; ks < 4; ks++) {
                uint32_t kb[4][4];
                #pragma unroll
                for (int p = 0; p < 4; p++)
                    LDSM4(kb[p], bufK + ks * 32 + p * (16 * APD * 2));
                #pragma unroll
                for (int nt = 0; nt < 8; nt++)
                    MMA_F16(sc[nt], qf[ks][0], qf[ks][1], qf[ks][2], qf[ks][3],
                            kb[nt >> 1][nt & 1], kb[nt >> 1][2 + (nt & 1)]);
            }

            if (causal && keybase + 63 > rowmin) {
                const int r0g = rowmin + g, r1g = r0g + 8;
                #pragma unroll
                for (int nt = 0; nt < 8; nt++) {
                    int c0 = keybase + nt * 8 + 2 * t, c1 = c0 + 1;
                    if (c0 > r0g) sc[nt][0] = -INFINITY;
                    if (c1 > r0g) sc[nt][1] = -INFINITY;
                    if (c0 > r1g) sc[nt][2] = -INFINITY;
                    if (c1 > r1g) sc[nt][3] = -INFINITY;
                }
            }

            // ---- online softmax (exp2 domain) ----
            float mx0 = m0, mx1 = m1;
            #pragma unroll
            for (int nt = 0; nt < 8; nt++) {
                mx0 = fmaxf(mx0, fmaxf(sc[nt][0], sc[nt][1]));
                mx1 = fmaxf(mx1, fmaxf(sc[nt][2], sc[nt][3]));
            }
            mx0 = fmaxf(mx0, __shfl_xor_sync(0xffffffffu, mx0, 1));
            mx0 = fmaxf(mx0, __shfl_xor_sync(0xffffffffu, mx0, 2));
            mx1 = fmaxf(mx1, __shfl_xor_sync(0xffffffffu, mx1, 1));
            mx1 = fmaxf(mx1, __shfl_xor_sync(0xffffffffu, mx1, 2));
            float a0 = exp2f(m0 - mx0), a1 = exp2f(m1 - mx1);
            m0 = mx0; m1 = mx1;

            float s0 = 0.f, s1 = 0.f;
            uint32_t ph[8][2];
            #pragma unroll
            for (int nt = 0; nt < 8; nt++) {
                float p00 = exp2f(sc[nt][0] - m0);
                float p01 = exp2f(sc[nt][1] - m0);
                float p10 = exp2f(sc[nt][2] - m1);
                float p11 = exp2f(sc[nt][3] - m1);
                s0 += p00 + p01; s1 += p10 + p11;
                ph[nt][0] = packh2(p00, p01);
                ph[nt][1] = packh2(p10, p11);
                oa[nt][0] *= a0; oa[nt][1] *= a0;
                oa[nt][2] *= a1; oa[nt][3] *= a1;
            }
            l0 = l0 * a0 + s0;
            l1 = l1 * a1 + s1;

            // ---- O += P V ----
            #pragma unroll
            for (int ks = 0; ks < 4; ks++) {
                const uint32_t pf0 = ph[2 * ks][0],     pf1 = ph[2 * ks][1];
                const uint32_t pf2 = ph[2 * ks + 1][0], pf3 = ph[2 * ks + 1][1];
                #pragma unroll
                for (int j = 0; j < 4; j++) {
                    uint32_t vq[4];
                    LDSM4T(vq, bufV + ks * (16 * APD * 2) + j * 32);
                    MMA_F16(oa[2 * j + 0], pf0, pf1, pf2, pf3, vq[0], vq[1]);
                    MMA_F16(oa[2 * j + 1], pf0, pf1, pf2, pf3, vq[2], vq[3]);
                }
            }
        }
    }
#undef ISSUE_KV

    l0 += __shfl_xor_sync(0xffffffffu, l0, 1);
    l0 += __shfl_xor_sync(0xffffffffu, l0, 2);
    l1 += __shfl_xor_sync(0xffffffffu, l1, 1);
    l1 += __shfl_xor_sync(0xffffffffu, l1, 2);

    float i0 = 1.f / l0, i1 = 1.f / l1;
    __half* ob = g_att + (size_t)(b * SS + qt * QT) * DD + h * DH;
    #pragma unroll
    for (int nt = 0; nt < 8; nt++) {
        *(__half2*)(ob + (size_t)r0 * DD + nt * 8 + 2 * t) =
            __floats2half2_rn(oa[nt][0] * i0, oa[nt][1] * i0);
        *(__half2*)(ob + (size_t)r1 * DD + nt * 8 + 2 * t) =
            __floats2half2_rn(oa[nt][2] * i1, oa[nt][3] * i1);
    }
}

// ---------------------------------------------------------------------------
extern "C" void kernel_launch(void* const* d_in, const int* in_sizes, int n_in,
                              void* d_out, int out_size)
{
    const float* x     = (const float*)d_in[0];
    const float* w_in  = (const float*)d_in[1];
    const float* b_in  = (const float*)d_in[2];
    const float* w_out = (const float*)d_in[3];
    const float* b_out = (const float*)d_in[4];
    const int*   cmask = (const int*)d_in[5];

    __half *qkv, *att, *xh, *w1h, *w2h;
    cudaGetSymbolAddress((void**)&qkv, g_qkv);
    cudaGetSymbolAddress((void**)&att, g_att);
    cudaGetSymbolAddress((void**)&xh,  g_xh);
    cudaGetSymbolAddress((void**)&w1h, g_w1h);
    cudaGetSymbolAddress((void**)&w2h, g_w2h);

    cudaFuncSetAttribute((const void*)gemm_f16mma<1>,
                         cudaFuncAttributeMaxDynamicSharedMemorySize, GSMEM_BYTES);
    cudaFuncSetAttribute((const void*)gemm_f16mma<0>,
                         cudaFuncAttributeMaxDynamicSharedMemorySize, GSMEM_BYTES);
    cudaFuncSetAttribute((const void*)flash_attn_f16,
                         cudaFuncAttributeMaxDynamicSharedMemorySize, ASMEM_BYTES);

    // 0) convert x, w_in, w_out to fp16 (one launch)
    {
        int tot = MROWS * DD / 4 + N1 * DD / 4 + DD * DD / 4;
        toh3<<<(tot + 255) / 256, 256>>>(x, xh, w_in, w1h, w_out, w2h);
    }

    // 1) QKV projection -> fp16 qkv
    gemm_f16mma<1><<<dim3(N1 / 128, MROWS / 128), 256, GSMEM_BYTES>>>(
        xh, w1h, b_in, qkv, MROWS, N1, DD);

    // 2) Causal multi-head flash attention (fp16 TC, 128-key tiles)
    flash_attn_f16<<<dim3(SS / QT, HH, BB), 256, ASMEM_BYTES>>>(cmask);

    // 3) Output projection -> fp32 out
    gemm_f16mma<0><<<dim3(DD / 128, MROWS / 128), 256, GSMEM_BYTES>>>(
        att, w2h, b_out, (float*)d_out, MROWS, DD, DD);
}